// round 12
// baseline (speedup 1.0000x reference)
#include <cuda_runtime.h>
#include <math.h>

// Shapes (fixed by the problem)
#define H    768
#define T    512
#define NC   8
#define NCT  4096
#define NL   8921
#define NN   4
#define RSPLIT 1115      // lw rows 1115*c (c=1..7) are split across chunks c-1/c

// Partition config
#define NSUB     32      // 512 rows per chunk -> 32 sub-blocks of 16 rows
#define SUBROWS  16
#define SLICELEN 24
#define NSLICE   372     // ceil(8921/24)
#define H4       192     // H / 4

#define NB_ENC (NC * NSUB)        // 256 encoding blocks
#define NB_LW  NSLICE             // 372 lw blocks
#define NBLK   (NB_ENC + NB_LW)

// Accumulator slots (zero-init; last block re-zeros -> self-cleaning):
//   [c*H)        c=0..7  : B_c  per-chunk enc column sums
//   [(8+c)*H)    c=0..7  : L_c  per-chunk lw full-row sums
//   [(15+c)*H)   c=1..7  : lw[RSPLIT*c][k] split boundary rows
#define NSLOT 23
__device__ float g_acc[NSLOT * H];
__device__ unsigned g_ticket = 0;   // last-block election; self-resetting

// note_end_chunk_ids may be int32 or int64 on device; detect from word pattern.
__device__ __forceinline__ void load_ids(const int* __restrict__ w, int ids[4]) {
    int a0 = w[0], a1 = w[1], a2 = w[2], a3 = w[3];
    bool maybe64 = (a1 == 0 && a3 == 0 && a0 >= 0 && a0 < NC && a2 >= a0 && a2 < NC);
    if (maybe64) {
        int b2 = w[4], b2h = w[5], b3 = w[6], b3h = w[7];
        if (b2h == 0 && b3h == 0 && b2 >= a2 && b2 < NC && b3 >= b2 && b3 < NC) {
            ids[0] = a0; ids[1] = a2; ids[2] = b2; ids[3] = b3;
            return;
        }
    }
    ids[0] = a0; ids[1] = a1; ids[2] = a2; ids[3] = a3;
}

__device__ __forceinline__ void acc4(float4& s, const float4 v) {
    s.x += v.x; s.y += v.y; s.z += v.z; s.w += v.w;
}

__device__ __forceinline__ float4 ldcs4(const float4* p) {
    return __ldcs(p);   // streaming load, evict-first: data is touched once
}

__device__ __forceinline__ void red4(float* dst, int k4, const float4 v) {
    atomicAdd(dst + k4 * 4 + 0, v.x);
    atomicAdd(dst + k4 * 4 + 1, v.y);
    atomicAdd(dst + k4 * 4 + 2, v.z);
    atomicAdd(dst + k4 * 4 + 3, v.w);
}

// Single fused kernel: streaming block-sums (relaxed REDG accumulate),
// then last-block election via ONE acq_rel ticket atomic per block
// (cumulativity through __syncthreads gives visibility of all REDGs —
// no per-thread __threadfence, which was the R5 disaster).
__global__ void __launch_bounds__(192)
k_main(const float* __restrict__ enc, const float* __restrict__ lw,
       const int* __restrict__ idw, float* __restrict__ out) {
    int b = blockIdx.x;
    int t = threadIdx.x;           // k4 lane, 0..191
    if (b < NB_ENC) {
        int chunk = b >> 5, sub = b & 31;
        const float4* p = (const float4*)enc + (size_t)(chunk * T + sub * SUBROWS) * H4 + t;
        float4 v[SUBROWS];
        #pragma unroll
        for (int r = 0; r < SUBROWS; ++r) v[r] = ldcs4(p + (size_t)r * H4);
        #pragma unroll
        for (int s = 8; s >= 1; s >>= 1)
            #pragma unroll
            for (int i = 0; i < s; ++i) acc4(v[i], v[i + s]);
        red4(g_acc + chunk * H, t, v[0]);
    } else {
        int is = b - NB_ENC;
        int i0 = is * SLICELEN;
        int i1 = min(i0 + SLICELEN, NL);
        int i = i0;
        while (i < i1) {
            int c   = i / RSPLIT;
            int rem = i - c * RSPLIT;
            if (rem == 0 && c >= 1 && c <= 7) {
                // split boundary row: stash its value in slot 15+c
                float4 v = ldcs4((const float4*)lw + (size_t)i * H4 + t);
                red4(g_acc + (15 + c) * H, t, v);
                ++i;
                continue;
            }
            int ch = (c > 7) ? 7 : c;                             // row 8920 -> chunk 7
            int segend = min(i1, (c + 1) * RSPLIT);
            const float4* p = (const float4*)lw + (size_t)i * H4 + t;
            int n = segend - i;
            float4 a[8];
            #pragma unroll
            for (int j = 0; j < 8; ++j) a[j] = make_float4(0.f, 0.f, 0.f, 0.f);
            int r = 0;
            for (; r + 8 <= n; r += 8) {
                float4 v0 = ldcs4(p + (size_t)(r + 0) * H4);
                float4 v1 = ldcs4(p + (size_t)(r + 1) * H4);
                float4 v2 = ldcs4(p + (size_t)(r + 2) * H4);
                float4 v3 = ldcs4(p + (size_t)(r + 3) * H4);
                float4 v4 = ldcs4(p + (size_t)(r + 4) * H4);
                float4 v5 = ldcs4(p + (size_t)(r + 5) * H4);
                float4 v6 = ldcs4(p + (size_t)(r + 6) * H4);
                float4 v7 = ldcs4(p + (size_t)(r + 7) * H4);
                acc4(a[0], v0); acc4(a[1], v1); acc4(a[2], v2); acc4(a[3], v3);
                acc4(a[4], v4); acc4(a[5], v5); acc4(a[6], v6); acc4(a[7], v7);
            }
            for (; r < n; ++r) acc4(a[r & 7], ldcs4(p + (size_t)r * H4));
            #pragma unroll
            for (int j = 0; j < 4; ++j) acc4(a[j], a[j + 4]);
            acc4(a[0], a[2]); acc4(a[1], a[3]); acc4(a[0], a[1]);
            red4(g_acc + (8 + ch) * H, t, a[0]);
            i = segend;
        }
    }

    // ── Last-block election: bar.sync + ONE acq_rel ticket per block ───
    __syncthreads();
    __shared__ int s_last;
    if (t == 0) {
        unsigned old;
        asm volatile("atom.acq_rel.gpu.global.add.u32 %0, [%1], 1;"
                     : "=r"(old) : "l"(&g_ticket) : "memory");
        s_last = (old == NBLK - 1u);
    }
    __syncthreads();
    if (!s_last) return;

    // ── Final combine (last block; all inputs L2-hot in g_acc) ─────────
    int ids[4];
    load_ids(idw, ids);
    float v[4][8];
    #pragma unroll
    for (int c = 0; c < 8; ++c) {
        int cnt = 0;
        #pragma unroll
        for (int n = 0; n < 4; ++n) cnt += (ids[n] < c);
        float inv = (cnt > 0) ? 1.f / (float)cnt : 0.f;
        #pragma unroll
        for (int n = 0; n < 4; ++n)
            v[n][c] = (cnt == 0) ? 0.25f : ((ids[n] < c) ? inv : 0.f);
    }

    #pragma unroll
    for (int kk = 0; kk < 4; ++kk) {
        int k = kk * 192 + t;

        float B[8], L[8], lwr[8];
        #pragma unroll
        for (int c = 0; c < 8; ++c) {
            B[c] = __ldcg(&g_acc[c * H + k]);
            L[c] = __ldcg(&g_acc[(8 + c) * H + k]);
        }
        #pragma unroll
        for (int c = 1; c <= 7; ++c)
            lwr[c] = __ldcg(&g_acc[(15 + c) * H + k]);

        float P[9];
        P[0] = 0.f;
        #pragma unroll
        for (int c = 0; c < 8; ++c) P[c + 1] = P[c] + B[c];
        float E = P[8];

        // S_c[k] = L_c*E + split-row boundary terms
        float S[8];
        #pragma unroll
        for (int c = 0; c < 8; ++c) {
            float s = L[c] * E;
            if (c >= 1) s += lwr[c] * (E - P[c]);
            if (c <= 6) s += lwr[c + 1] * P[c + 1];
            S[c] = s;
        }

        #pragma unroll
        for (int n = 0; n < 4; ++n) {
            float sc = 0.f;
            #pragma unroll
            for (int c = 0; c < 8; ++c) sc += v[n][c] * S[c];
            out[n * H + k] = 1.f / (1.f + expf(-sc));
        }

        // Self-clean for the next graph replay.
        #pragma unroll
        for (int c = 0; c < NSLOT; ++c) g_acc[c * H + k] = 0.f;
    }

    __syncthreads();
    if (t == 0) g_ticket = 0;   // reset election (visible after kernel boundary)
}

extern "C" void kernel_launch(void* const* d_in, const int* in_sizes, int n_in,
                              void* d_out, int out_size) {
    // Locate inputs by element count; fall back to declared order.
    int ie = 0, ilw = 2, iid = 3;
    int hnl_seen = 0;
    for (int i = 0; i < n_in; ++i) {
        long long sz = in_sizes[i];
        if (sz == (long long)NCT * H) ie = i;
        else if (sz == (long long)H * NL) { if (hnl_seen++) ilw = i; }
        else if (sz == NN) iid = i;
    }
    const float* enc = (const float*)d_in[ie];
    const float* lw  = (const float*)d_in[ilw];
    const int*   idw = (const int*)d_in[iid];

    k_main<<<NBLK, 192>>>(enc, lw, idw, (float*)d_out);
}

// round 14
// speedup vs baseline: 1.1379x; 1.1379x over previous
#include <cuda_runtime.h>
#include <math.h>

// Shapes (fixed by the problem)
#define H    768
#define T    512
#define NC   8
#define NCT  4096
#define NL   8921
#define NN   4
#define RSPLIT 1115      // lw rows 1115*c (c=1..7) are split across chunks c-1/c

#define H4   192         // H / 4
#define VTOT (NCT + NL)  // 13017 virtual rows (enc then lw)
#define RPB  24          // rows per block
#define NBLK 544         // 544*24 = 13056 >= 13017; < 592 => single wave

// Accumulator slots (zero-init; k_final re-zeros -> self-cleaning):
//   [c*H)      c=0..7 : B_c per-chunk enc column sums
//   [(8+c)*H)  c=0..7 : L_c per-chunk lw full-row sums
#define NSLOT 16
__device__ float g_acc[NSLOT * H];

// note_end_chunk_ids may be int32 or int64 on device; detect from word pattern.
__device__ __forceinline__ void load_ids(const int* __restrict__ w, int ids[4]) {
    int a0 = w[0], a1 = w[1], a2 = w[2], a3 = w[3];
    bool maybe64 = (a1 == 0 && a3 == 0 && a0 >= 0 && a0 < NC && a2 >= a0 && a2 < NC);
    if (maybe64) {
        int b2 = w[4], b2h = w[5], b3 = w[6], b3h = w[7];
        if (b2h == 0 && b3h == 0 && b2 >= a2 && b2 < NC && b3 >= b2 && b3 < NC) {
            ids[0] = a0; ids[1] = a2; ids[2] = b2; ids[3] = b3;
            return;
        }
    }
    ids[0] = a0; ids[1] = a1; ids[2] = a2; ids[3] = a3;
}

__device__ __forceinline__ void acc4(float4& s, const float4 v) {
    s.x += v.x; s.y += v.y; s.z += v.z; s.w += v.w;
}

__device__ __forceinline__ float4 ldcs4(const float4* p) {
    return __ldcs(p);   // streaming load, evict-first: data is touched once
}

__device__ __forceinline__ void red4(float* dst, int k4, const float4 v) {
    atomicAdd(dst + k4 * 4 + 0, v.x);
    atomicAdd(dst + k4 * 4 + 1, v.y);
    atomicAdd(dst + k4 * 4 + 2, v.z);
    atomicAdd(dst + k4 * 4 + 3, v.w);
}

// Sum n rows (n <= 24) starting at p (row stride H4), REDG into slot.
__device__ __forceinline__ void sum_rows(const float4* p, int n, float* slot, int t) {
    float4 a[8];
    #pragma unroll
    for (int j = 0; j < 8; ++j) a[j] = make_float4(0.f, 0.f, 0.f, 0.f);
    int r = 0;
    for (; r + 8 <= n; r += 8) {
        float4 v0 = ldcs4(p + (size_t)(r + 0) * H4);
        float4 v1 = ldcs4(p + (size_t)(r + 1) * H4);
        float4 v2 = ldcs4(p + (size_t)(r + 2) * H4);
        float4 v3 = ldcs4(p + (size_t)(r + 3) * H4);
        float4 v4 = ldcs4(p + (size_t)(r + 4) * H4);
        float4 v5 = ldcs4(p + (size_t)(r + 5) * H4);
        float4 v6 = ldcs4(p + (size_t)(r + 6) * H4);
        float4 v7 = ldcs4(p + (size_t)(r + 7) * H4);
        acc4(a[0], v0); acc4(a[1], v1); acc4(a[2], v2); acc4(a[3], v3);
        acc4(a[4], v4); acc4(a[5], v5); acc4(a[6], v6); acc4(a[7], v7);
    }
    for (; r < n; ++r) acc4(a[r & 7], ldcs4(p + (size_t)r * H4));
    #pragma unroll
    for (int j = 0; j < 4; ++j) acc4(a[j], a[j + 4]);
    acc4(a[0], a[2]); acc4(a[1], a[3]); acc4(a[0], a[1]);
    red4(slot, t, a[0]);
}

// Streaming pass over a unified 13017-row virtual array (enc rows then lw
// rows), 24 rows per block -> 544 uniform blocks = exactly one wave at
// 4 blocks/SM. Segments by destination slot inside the block.
__global__ void __launch_bounds__(192)
k_main(const float* __restrict__ enc, const float* __restrict__ lw) {
    int t  = threadIdx.x;          // k4 lane, 0..191
    int v  = blockIdx.x * RPB;
    int v1 = min(v + RPB, VTOT);

    while (v < v1) {
        if (v < NCT) {
            // encoding rows; chunk = v/512
            int chunk = v >> 9;
            int vend  = min(v1, min(NCT, (chunk + 1) << 9));
            sum_rows((const float4*)enc + (size_t)v * H4 + t, vend - v,
                     g_acc + chunk * H, t);
            v = vend;
        } else {
            int u   = v - NCT;
            int c   = u / RSPLIT;
            int rem = u - c * RSPLIT;
            if (rem == 0 && c >= 1 && c <= 7) { ++v; continue; }  // boundary row: k_final reads it
            int ch   = (c > 7) ? 7 : c;                           // row 8920 -> chunk 7
            int uend = min(v1 - NCT, (c + 1) * RSPLIT);
            sum_rows((const float4*)lw + (size_t)u * H4 + t, uend - u,
                     g_acc + (8 + ch) * H, t);
            v = NCT + uend;
        }
    }
}

// Final combine, PDL-overlapped: all k_main-independent loads happen BEFORE
// cudaGridDependencySynchronize(); only g_acc reads after. Re-zeros g_acc.
__global__ void __launch_bounds__(768)
k_final(const float* __restrict__ lw, const int* __restrict__ idw,
        float* __restrict__ out) {
    int k = threadIdx.x;    // grid = 1, 768 threads

    // ── Pre-sync phase (independent of k_main) ──────────────────────────
    int ids[4];
    load_ids(idw, ids);
    float v[4][8];
    #pragma unroll
    for (int c = 0; c < 8; ++c) {
        int cnt = 0;
        #pragma unroll
        for (int n = 0; n < 4; ++n) cnt += (ids[n] < c);
        float inv = (cnt > 0) ? 1.f / (float)cnt : 0.f;
        #pragma unroll
        for (int n = 0; n < 4; ++n)
            v[n][c] = (cnt == 0) ? 0.25f : ((ids[n] < c) ? inv : 0.f);
    }
    float lwr[8];   // lw[RSPLIT*c][k] for c=1..7
    #pragma unroll
    for (int c = 1; c <= 7; ++c)
        lwr[c] = __ldg(&lw[(size_t)(RSPLIT * c) * H + k]);

    // ── Wait for k_main (launch-dependency machinery; completes with
    //    stream-order memory visibility, no threadfence anywhere) ────────
    cudaGridDependencySynchronize();

    float B[8], L[8];
    #pragma unroll
    for (int c = 0; c < 8; ++c) {
        B[c] = g_acc[c * H + k];
        L[c] = g_acc[(8 + c) * H + k];
    }
    // Self-clean for the next graph replay.
    #pragma unroll
    for (int c = 0; c < NSLOT; ++c) g_acc[c * H + k] = 0.f;

    float P[9];
    P[0] = 0.f;
    #pragma unroll
    for (int c = 0; c < 8; ++c) P[c + 1] = P[c] + B[c];
    float E = P[8];

    // S_c[k] = L_c*E + split-row boundary terms
    float S[8];
    #pragma unroll
    for (int c = 0; c < 8; ++c) {
        float s = L[c] * E;
        if (c >= 1) s += lwr[c] * (E - P[c]);
        if (c <= 6) s += lwr[c + 1] * P[c + 1];
        S[c] = s;
    }

    #pragma unroll
    for (int n = 0; n < 4; ++n) {
        float sc = 0.f;
        #pragma unroll
        for (int c = 0; c < 8; ++c) sc += v[n][c] * S[c];
        out[n * H + k] = 1.f / (1.f + expf(-sc));
    }
}

extern "C" void kernel_launch(void* const* d_in, const int* in_sizes, int n_in,
                              void* d_out, int out_size) {
    // Locate inputs by element count; fall back to declared order.
    int ie = 0, ilw = 2, iid = 3;
    int hnl_seen = 0;
    for (int i = 0; i < n_in; ++i) {
        long long sz = in_sizes[i];
        if (sz == (long long)NCT * H) ie = i;
        else if (sz == (long long)H * NL) { if (hnl_seen++) ilw = i; }
        else if (sz == NN) iid = i;
    }
    const float* enc = (const float*)d_in[ie];
    const float* lw  = (const float*)d_in[ilw];
    const int*   idw = (const int*)d_in[iid];

    k_main<<<NBLK, 192>>>(enc, lw);

    // PDL launch: k_final spins up while k_main drains. Fallback keeps
    // correctness independent of PDL.
    cudaLaunchAttribute attr[1] = {};
    attr[0].id = cudaLaunchAttributeProgrammaticStreamSerialization;
    attr[0].val.programmaticStreamSerializationAllowed = 1;

    cudaLaunchConfig_t cfg = {};
    cfg.gridDim  = dim3(1, 1, 1);
    cfg.blockDim = dim3(768, 1, 1);
    cfg.dynamicSmemBytes = 0;
    cfg.stream = (cudaStream_t)0;
    cfg.attrs = attr;
    cfg.numAttrs = 1;

    cudaError_t e = cudaLaunchKernelEx(&cfg, k_final, lw, idw, (float*)d_out);
    if (e != cudaSuccess) {
        (void)cudaGetLastError();   // clear sticky error before fallback
        k_final<<<1, 768>>>(lw, idw, (float*)d_out);
    }
}

// round 15
// speedup vs baseline: 1.1630x; 1.0220x over previous
#include <cuda_runtime.h>
#include <math.h>

// Shapes (fixed by the problem)
#define H    768
#define T    512
#define NC   8
#define NCT  4096
#define NL   8921
#define NN   4
#define RSPLIT 1115      // lw rows 1115*c (c=1..7) are split across chunks c-1/c

#define H4   192         // H / 4
#define VTOT (NCT + NL)  // 13017 virtual rows (enc then lw)
#define RPB  24          // rows per block
#define NBLK 544         // 544*24 = 13056 >= 13017; < 592 => single wave

// Accumulator slots (zero-init; k_final re-zeros -> self-cleaning):
//   [c*H)      c=0..7 : B_c per-chunk enc column sums
//   [(8+c)*H)  c=0..7 : L_c per-chunk lw full-row sums
#define NSLOT 16
__device__ float g_acc[NSLOT * H];

// note_end_chunk_ids may be int32 or int64 on device; detect from word pattern.
__device__ __forceinline__ void load_ids(const int* __restrict__ w, int ids[4]) {
    int a0 = w[0], a1 = w[1], a2 = w[2], a3 = w[3];
    bool maybe64 = (a1 == 0 && a3 == 0 && a0 >= 0 && a0 < NC && a2 >= a0 && a2 < NC);
    if (maybe64) {
        int b2 = w[4], b2h = w[5], b3 = w[6], b3h = w[7];
        if (b2h == 0 && b3h == 0 && b2 >= a2 && b2 < NC && b3 >= b2 && b3 < NC) {
            ids[0] = a0; ids[1] = a2; ids[2] = b2; ids[3] = b3;
            return;
        }
    }
    ids[0] = a0; ids[1] = a1; ids[2] = a2; ids[3] = a3;
}

__device__ __forceinline__ void acc4(float4& s, const float4 v) {
    s.x += v.x; s.y += v.y; s.z += v.z; s.w += v.w;
}

// Default cached load: with a 40 MB working set inside the ~126 MB L2,
// graph replays hit L2 instead of HBM. (__ldcs evict-first was discarding
// the lines and forcing every replay back to DRAM.)
__device__ __forceinline__ float4 ld4(const float4* p) {
    return __ldg(p);
}

__device__ __forceinline__ void red4(float* dst, int k4, const float4 v) {
    atomicAdd(dst + k4 * 4 + 0, v.x);
    atomicAdd(dst + k4 * 4 + 1, v.y);
    atomicAdd(dst + k4 * 4 + 2, v.z);
    atomicAdd(dst + k4 * 4 + 3, v.w);
}

// Sum n rows (n <= 24) starting at p (row stride H4), REDG into slot.
__device__ __forceinline__ void sum_rows(const float4* p, int n, float* slot, int t) {
    float4 a[8];
    #pragma unroll
    for (int j = 0; j < 8; ++j) a[j] = make_float4(0.f, 0.f, 0.f, 0.f);
    int r = 0;
    for (; r + 8 <= n; r += 8) {
        float4 v0 = ld4(p + (size_t)(r + 0) * H4);
        float4 v1 = ld4(p + (size_t)(r + 1) * H4);
        float4 v2 = ld4(p + (size_t)(r + 2) * H4);
        float4 v3 = ld4(p + (size_t)(r + 3) * H4);
        float4 v4 = ld4(p + (size_t)(r + 4) * H4);
        float4 v5 = ld4(p + (size_t)(r + 5) * H4);
        float4 v6 = ld4(p + (size_t)(r + 6) * H4);
        float4 v7 = ld4(p + (size_t)(r + 7) * H4);
        acc4(a[0], v0); acc4(a[1], v1); acc4(a[2], v2); acc4(a[3], v3);
        acc4(a[4], v4); acc4(a[5], v5); acc4(a[6], v6); acc4(a[7], v7);
    }
    for (; r < n; ++r) acc4(a[r & 7], ld4(p + (size_t)r * H4));
    #pragma unroll
    for (int j = 0; j < 4; ++j) acc4(a[j], a[j + 4]);
    acc4(a[0], a[2]); acc4(a[1], a[3]); acc4(a[0], a[1]);
    red4(slot, t, a[0]);
}

// Streaming pass over a unified 13017-row virtual array (enc rows then lw
// rows), 24 rows per block -> 544 uniform blocks = exactly one wave at
// 4 blocks/SM. Segments by destination slot inside the block.
__global__ void __launch_bounds__(192)
k_main(const float* __restrict__ enc, const float* __restrict__ lw) {
    int t  = threadIdx.x;          // k4 lane, 0..191
    int v  = blockIdx.x * RPB;
    int v1 = min(v + RPB, VTOT);

    while (v < v1) {
        if (v < NCT) {
            // encoding rows; chunk = v/512
            int chunk = v >> 9;
            int vend  = min(v1, min(NCT, (chunk + 1) << 9));
            sum_rows((const float4*)enc + (size_t)v * H4 + t, vend - v,
                     g_acc + chunk * H, t);
            v = vend;
        } else {
            int u   = v - NCT;
            int c   = u / RSPLIT;
            int rem = u - c * RSPLIT;
            if (rem == 0 && c >= 1 && c <= 7) { ++v; continue; }  // boundary row: k_final reads it
            int ch   = (c > 7) ? 7 : c;                           // row 8920 -> chunk 7
            int uend = min(v1 - NCT, (c + 1) * RSPLIT);
            sum_rows((const float4*)lw + (size_t)u * H4 + t, uend - u,
                     g_acc + (8 + ch) * H, t);
            v = NCT + uend;
        }
    }
}

// Final combine, PDL-overlapped: all k_main-independent loads happen BEFORE
// cudaGridDependencySynchronize(); only g_acc reads after. Re-zeros g_acc.
__global__ void __launch_bounds__(768)
k_final(const float* __restrict__ lw, const int* __restrict__ idw,
        float* __restrict__ out) {
    int k = threadIdx.x;    // grid = 1, 768 threads

    // ── Pre-sync phase (independent of k_main) ──────────────────────────
    int ids[4];
    load_ids(idw, ids);
    float v[4][8];
    #pragma unroll
    for (int c = 0; c < 8; ++c) {
        int cnt = 0;
        #pragma unroll
        for (int n = 0; n < 4; ++n) cnt += (ids[n] < c);
        float inv = (cnt > 0) ? 1.f / (float)cnt : 0.f;
        #pragma unroll
        for (int n = 0; n < 4; ++n)
            v[n][c] = (cnt == 0) ? 0.25f : ((ids[n] < c) ? inv : 0.f);
    }
    float lwr[8];   // lw[RSPLIT*c][k] for c=1..7
    #pragma unroll
    for (int c = 1; c <= 7; ++c)
        lwr[c] = __ldg(&lw[(size_t)(RSPLIT * c) * H + k]);

    // ── Wait for k_main (launch-dependency machinery; completes with
    //    stream-order memory visibility, no threadfence anywhere) ────────
    cudaGridDependencySynchronize();

    float B[8], L[8];
    #pragma unroll
    for (int c = 0; c < 8; ++c) {
        B[c] = g_acc[c * H + k];
        L[c] = g_acc[(8 + c) * H + k];
    }
    // Self-clean for the next graph replay.
    #pragma unroll
    for (int c = 0; c < NSLOT; ++c) g_acc[c * H + k] = 0.f;

    float P[9];
    P[0] = 0.f;
    #pragma unroll
    for (int c = 0; c < 8; ++c) P[c + 1] = P[c] + B[c];
    float E = P[8];

    // S_c[k] = L_c*E + split-row boundary terms
    float S[8];
    #pragma unroll
    for (int c = 0; c < 8; ++c) {
        float s = L[c] * E;
        if (c >= 1) s += lwr[c] * (E - P[c]);
        if (c <= 6) s += lwr[c + 1] * P[c + 1];
        S[c] = s;
    }

    #pragma unroll
    for (int n = 0; n < 4; ++n) {
        float sc = 0.f;
        #pragma unroll
        for (int c = 0; c < 8; ++c) sc += v[n][c] * S[c];
        out[n * H + k] = 1.f / (1.f + expf(-sc));
    }
}

extern "C" void kernel_launch(void* const* d_in, const int* in_sizes, int n_in,
                              void* d_out, int out_size) {
    // Locate inputs by element count; fall back to declared order.
    int ie = 0, ilw = 2, iid = 3;
    int hnl_seen = 0;
    for (int i = 0; i < n_in; ++i) {
        long long sz = in_sizes[i];
        if (sz == (long long)NCT * H) ie = i;
        else if (sz == (long long)H * NL) { if (hnl_seen++) ilw = i; }
        else if (sz == NN) iid = i;
    }
    const float* enc = (const float*)d_in[ie];
    const float* lw  = (const float*)d_in[ilw];
    const int*   idw = (const int*)d_in[iid];

    k_main<<<NBLK, 192>>>(enc, lw);

    // PDL launch: k_final spins up while k_main drains. Fallback keeps
    // correctness independent of PDL.
    cudaLaunchAttribute attr[1] = {};
    attr[0].id = cudaLaunchAttributeProgrammaticStreamSerialization;
    attr[0].val.programmaticStreamSerializationAllowed = 1;

    cudaLaunchConfig_t cfg = {};
    cfg.gridDim  = dim3(1, 1, 1);
    cfg.blockDim = dim3(768, 1, 1);
    cfg.dynamicSmemBytes = 0;
    cfg.stream = (cudaStream_t)0;
    cfg.attrs = attr;
    cfg.numAttrs = 1;

    cudaError_t e = cudaLaunchKernelEx(&cfg, k_final, lw, idw, (float*)d_out);
    if (e != cudaSuccess) {
        (void)cudaGetLastError();   // clear sticky error before fallback
        k_final<<<1, 768>>>(lw, idw, (float*)d_out);
    }
}